// round 1
// baseline (speedup 1.0000x reference)
#include <cuda_runtime.h>
#include <math.h>

#define BATCH 2048
#define DM 256
#define NF 32768
#define NB 8

#define BM 128
#define BN 128
#define BK 16

// ---------------- device scratch (no allocations allowed) ----------------
__device__ float g_blockacc[(size_t)NB * BATCH * DM];  // 16 MB block partial preds
__device__ float g_wdn[NF];
__device__ float g_cw[NB];
__device__ float g_scale;
__device__ float g_normsum;
__device__ double g_l1;
__device__ double g_mse;
__device__ unsigned long long g_l0;

// ---------------- zero scratch ----------------
__global__ void k_zero() {
    size_t n = (size_t)NB * BATCH * DM;
    for (size_t i = (size_t)blockIdx.x * blockDim.x + threadIdx.x; i < n;
         i += (size_t)gridDim.x * blockDim.x)
        g_blockacc[i] = 0.f;
    if (blockIdx.x == 0 && threadIdx.x == 0) {
        g_normsum = 0.f; g_l1 = 0.0; g_mse = 0.0; g_l0 = 0ull;
    }
}

// ---------------- mean row norm of x ----------------
__global__ void k_xnorm(const float* __restrict__ x) {
    int warp = threadIdx.x >> 5, lane = threadIdx.x & 31;
    int row = blockIdx.x * 8 + warp;
    const float* xr = x + (size_t)row * DM;
    float s = 0.f;
#pragma unroll
    for (int i = 0; i < DM / 32; i++) { float v = xr[lane + 32 * i]; s += v * v; }
#pragma unroll
    for (int o = 16; o > 0; o >>= 1) s += __shfl_down_sync(0xffffffffu, s, o);
    if (lane == 0) atomicAdd(&g_normsum, sqrtf(s));
}

// ---------------- W_dec row norms ----------------
__global__ void k_wdn(const float* __restrict__ W_dec) {
    int warp = threadIdx.x >> 5, lane = threadIdx.x & 31;
    int row = blockIdx.x * 8 + warp;
    const float* wr = W_dec + (size_t)row * DM;
    float s = 0.f;
#pragma unroll
    for (int i = 0; i < DM / 32; i++) { float v = wr[lane + 32 * i]; s += v * v; }
#pragma unroll
    for (int o = 16; o > 0; o >>= 1) s += __shfl_down_sync(0xffffffffu, s, o);
    if (lane == 0) g_wdn[row] = sqrtf(s);
}

// ---------------- scalar prep: scale + cumulative-tail block weights ----------------
__global__ void k_prep(const float* __restrict__ running_avg, const float* __restrict__ bw) {
    float one_minus = (float)(1.0 - 0.99);
    float ra = 0.99f * running_avg[0] + one_minus * (g_normsum / (float)BATCH);
    g_scale = sqrtf((float)DM) / ra;
    float tot = 0.f;
    for (int j = NB - 1; j >= 0; j--) { tot += bw[j]; g_cw[j] = tot / (float)NB; }
}

// ---------------- main fused kernel ----------------
struct SmemMain {
    float As[BK][BM + 4];       // x tile, [k][row]
    float Bs[BK][BN + 4];       // W_enc / W_dec tile, [k][col]
    float actsS[BN][BM + 4];    // acts tile, [feature][row]
    float sbenc[BN];
    float swdn[BN];
    float scwf[BN];
    int   segs[BN];
    int   runs[BN + 1];
    int   nrun;
};

__global__ __launch_bounds__(256) void k_main(
    const float* __restrict__ x, const float* __restrict__ W_enc,
    const float* __restrict__ b_enc, const float* __restrict__ W_dec,
    const int* __restrict__ seg)
{
    extern __shared__ char smraw[];
    SmemMain& sm = *reinterpret_cast<SmemMain*>(smraw);
    const int tid = threadIdx.x;
    const int tx = tid & 15, ty = tid >> 4;
    const int f0 = blockIdx.x * BN;
    const int b0 = blockIdx.y * BM;
    const float scale = g_scale;

    if (tid < BN) {
        int f = f0 + tid;
        int s = seg[f];
        sm.segs[tid]  = s;
        sm.sbenc[tid] = b_enc[f];
        sm.swdn[tid]  = g_wdn[f];
        sm.scwf[tid]  = g_cw[s];
    }
    __syncthreads();
    if (tid == 0) {  // seg-run detection (seg is monotone; usually 1 run/tile)
        int n = 0; sm.runs[0] = 0;
        for (int k = 1; k < BN; k++)
            if (sm.segs[k] != sm.segs[k - 1]) sm.runs[++n] = k;
        sm.runs[n + 1] = BN; sm.nrun = n + 1;
    }

    // ---- GEMM1: raw = x_tile @ W_enc_tile, K = 256 ----
    float acc[8][8];
#pragma unroll
    for (int i = 0; i < 8; i++)
#pragma unroll
        for (int j = 0; j < 8; j++) acc[i][j] = 0.f;

    for (int k0 = 0; k0 < DM; k0 += BK) {
#pragma unroll
        for (int i = 0; i < 8; i++) {
            int idx = i * 256 + tid;
            int row = idx >> 4, kk = idx & 15;
            sm.As[kk][row] = x[(size_t)(b0 + row) * DM + k0 + kk];
        }
#pragma unroll
        for (int i = 0; i < 8; i++) {
            int idx = i * 256 + tid;
            int kk = idx >> 7, col = idx & 127;
            sm.Bs[kk][col] = W_enc[(size_t)(k0 + kk) * NF + f0 + col];
        }
        __syncthreads();
#pragma unroll
        for (int k = 0; k < BK; k++) {
            float4 a0 = *(const float4*)&sm.As[k][ty * 8];
            float4 a1 = *(const float4*)&sm.As[k][ty * 8 + 4];
            float4 bb0 = *(const float4*)&sm.Bs[k][tx * 8];
            float4 bb1 = *(const float4*)&sm.Bs[k][tx * 8 + 4];
            float a[8] = {a0.x, a0.y, a0.z, a0.w, a1.x, a1.y, a1.z, a1.w};
            float b[8] = {bb0.x, bb0.y, bb0.z, bb0.w, bb1.x, bb1.y, bb1.z, bb1.w};
#pragma unroll
            for (int i = 0; i < 8; i++)
#pragma unroll
                for (int j = 0; j < 8; j++) acc[i][j] = fmaf(a[i], b[j], acc[i][j]);
        }
        __syncthreads();
    }

    // ---- epilogue: relu + L1/L0 scalar terms, stash acts to smem ----
    float l1p = 0.f; int l0p = 0;
#pragma unroll
    for (int j = 0; j < 8; j++) {
        int col = tx * 8 + j;
        float be = sm.sbenc[col], wn = sm.swdn[col], cw = sm.scwf[col];
#pragma unroll
        for (int i = 0; i < 8; i++) {
            float act = fmaf(scale, acc[i][j], be);
            act = fmaxf(act, 0.f);
            if (act > 0.f) {
                l0p++;
                // log(a*wn + 0.1) - log(0.1) == log1p(10*a*wn)
                l1p += cw * __logf(fmaf(10.f * wn, act, 1.f));
            }
            sm.actsS[col][ty * 8 + i] = act;
        }
    }
#pragma unroll
    for (int o = 16; o > 0; o >>= 1) {
        l1p += __shfl_down_sync(0xffffffffu, l1p, o);
        l0p += __shfl_down_sync(0xffffffffu, l0p, o);
    }
    if ((tid & 31) == 0) {
        atomicAdd(&g_l1, (double)l1p);
        atomicAdd(&g_l0, (unsigned long long)l0p);
    }
    __syncthreads();

    // ---- GEMM2 per seg-run: acts @ W_dec -> atomic accumulate into block ----
    const int nrun = sm.nrun;
    for (int r = 0; r < nrun; r++) {
        const int ka = sm.runs[r], kb = sm.runs[r + 1];
        const int blk = sm.segs[ka];
        float* dstbase = g_blockacc + ((size_t)blk * BATCH + b0) * DM;
        for (int dh = 0; dh < 2; dh++) {
            float c[8][8];
#pragma unroll
            for (int i = 0; i < 8; i++)
#pragma unroll
                for (int j = 0; j < 8; j++) c[i][j] = 0.f;

            for (int k0 = ka & ~(BK - 1); k0 < kb; k0 += BK) {
#pragma unroll
                for (int i = 0; i < 8; i++) {
                    int idx = i * 256 + tid;
                    int kk = idx >> 7, col = idx & 127;
                    sm.Bs[kk][col] = W_dec[(size_t)(f0 + k0 + kk) * DM + dh * 128 + col];
                }
                __syncthreads();
#pragma unroll
                for (int k = 0; k < BK; k++) {
                    int kk = k0 + k;
                    if (kk >= ka && kk < kb) {  // uniform predicate (run bounds are CTA-uniform)
                        float4 a0 = *(const float4*)&sm.actsS[kk][ty * 8];
                        float4 a1 = *(const float4*)&sm.actsS[kk][ty * 8 + 4];
                        float4 bb0 = *(const float4*)&sm.Bs[k][tx * 8];
                        float4 bb1 = *(const float4*)&sm.Bs[k][tx * 8 + 4];
                        float a[8] = {a0.x, a0.y, a0.z, a0.w, a1.x, a1.y, a1.z, a1.w};
                        float b[8] = {bb0.x, bb0.y, bb0.z, bb0.w, bb1.x, bb1.y, bb1.z, bb1.w};
#pragma unroll
                        for (int i = 0; i < 8; i++)
#pragma unroll
                            for (int j = 0; j < 8; j++) c[i][j] = fmaf(a[i], b[j], c[i][j]);
                    }
                }
                __syncthreads();
            }
#pragma unroll
            for (int i = 0; i < 8; i++) {
                float* dst = dstbase + (size_t)(ty * 8 + i) * DM + dh * 128 + tx * 8;
#pragma unroll
                for (int j = 0; j < 8; j++) atomicAdd(&dst[j], c[i][j]);
            }
        }
    }
}

// ---------------- per-row cumulative-block MSE ----------------
__global__ void k_mse(const float* __restrict__ x, const float* __restrict__ b_dec,
                      const float* __restrict__ bw) {
    __shared__ float sbw[NB];
    __shared__ float red[8];
    int b = blockIdx.x, d = threadIdx.x;
    if (d < NB) sbw[d] = bw[d];
    __syncthreads();
    float xn = x[(size_t)b * DM + d] * g_scale;
    float cum = b_dec[d];
    float t = 0.f;
#pragma unroll
    for (int k = 0; k < NB; k++) {
        cum += g_blockacc[((size_t)k * BATCH + b) * DM + d];
        float diff = cum - xn;
        t += sbw[k] * diff * diff;
    }
#pragma unroll
    for (int o = 16; o > 0; o >>= 1) t += __shfl_down_sync(0xffffffffu, t, o);
    if ((d & 31) == 0) red[d >> 5] = t;
    __syncthreads();
    if (d < 8) {
        t = red[d];
#pragma unroll
        for (int o = 4; o > 0; o >>= 1) t += __shfl_down_sync(0xffu, t, o);
        if (d == 0) atomicAdd(&g_mse, (double)t);
    }
}

// ---------------- combine ----------------
__global__ void k_final(const float* __restrict__ l1_scale, float* __restrict__ out) {
    double mse = g_mse / ((double)NB * (double)BATCH);
    double l1  = g_l1 / (double)BATCH;
    float avg_l0 = (float)((double)g_l0 / (double)BATCH);
    float reg = l1_scale[0] * (avg_l0 < 100.0f ? (1.0f - 3e-4f) : (1.0f + 3e-4f));
    out[0] = (float)(mse + (double)reg * (double)l1);
}

// ---------------- launch ----------------
extern "C" void kernel_launch(void* const* d_in, const int* in_sizes, int n_in,
                              void* d_out, int out_size) {
    const float* x     = (const float*)d_in[0];
    const float* W_enc = (const float*)d_in[1];
    const float* b_enc = (const float*)d_in[2];
    const float* W_dec = (const float*)d_in[3];
    const float* b_dec = (const float*)d_in[4];
    const float* bw    = (const float*)d_in[5];
    const float* ravg  = (const float*)d_in[6];
    const float* l1s   = (const float*)d_in[7];
    const int*   seg   = (const int*)d_in[8];
    float* out = (float*)d_out;

    cudaFuncSetAttribute(k_main, cudaFuncAttributeMaxDynamicSharedMemorySize,
                         (int)sizeof(SmemMain));

    k_zero<<<2048, 256>>>();
    k_xnorm<<<BATCH / 8, 256>>>(x);
    k_wdn<<<NF / 8, 256>>>(W_dec);
    k_prep<<<1, 1>>>(ravg, bw);
    dim3 grid(NF / BN, BATCH / BM);
    k_main<<<grid, 256, sizeof(SmemMain)>>>(x, W_enc, b_enc, W_dec, seg);
    k_mse<<<BATCH, 256>>>(x, b_dec, bw);
    k_final<<<1, 1>>>(l1s, out);
}

// round 2
// speedup vs baseline: 1.0026x; 1.0026x over previous
#include <cuda_runtime.h>
#include <math.h>

#define BATCH 2048
#define DM 256
#define NF 32768
#define NB 8

#define BM 128
#define BN 128
#define BK 16

// ---------------- device scratch (no allocations allowed) ----------------
__device__ float g_blockacc[(size_t)NB * BATCH * DM];  // 16 MB block partial preds
__device__ float g_wdn[NF];
__device__ float g_cw[NB];
__device__ float g_scale;
__device__ float g_normsum;
__device__ double g_l1;
__device__ double g_mse;
__device__ unsigned long long g_l0;

// ---------------- zero scratch ----------------
__global__ void k_zero() {
    size_t n = (size_t)NB * BATCH * DM;
    for (size_t i = (size_t)blockIdx.x * blockDim.x + threadIdx.x; i < n;
         i += (size_t)gridDim.x * blockDim.x)
        g_blockacc[i] = 0.f;
    if (blockIdx.x == 0 && threadIdx.x == 0) {
        g_normsum = 0.f; g_l1 = 0.0; g_mse = 0.0; g_l0 = 0ull;
    }
}

// ---------------- mean row norm of x ----------------
__global__ void k_xnorm(const float* __restrict__ x) {
    int warp = threadIdx.x >> 5, lane = threadIdx.x & 31;
    int row = blockIdx.x * 8 + warp;
    const float* xr = x + (size_t)row * DM;
    float s = 0.f;
#pragma unroll
    for (int i = 0; i < DM / 32; i++) { float v = xr[lane + 32 * i]; s += v * v; }
#pragma unroll
    for (int o = 16; o > 0; o >>= 1) s += __shfl_down_sync(0xffffffffu, s, o);
    if (lane == 0) atomicAdd(&g_normsum, sqrtf(s));
}

// ---------------- W_dec row norms ----------------
__global__ void k_wdn(const float* __restrict__ W_dec) {
    int warp = threadIdx.x >> 5, lane = threadIdx.x & 31;
    int row = blockIdx.x * 8 + warp;
    const float* wr = W_dec + (size_t)row * DM;
    float s = 0.f;
#pragma unroll
    for (int i = 0; i < DM / 32; i++) { float v = wr[lane + 32 * i]; s += v * v; }
#pragma unroll
    for (int o = 16; o > 0; o >>= 1) s += __shfl_down_sync(0xffffffffu, s, o);
    if (lane == 0) g_wdn[row] = sqrtf(s);
}

// ---------------- scalar prep: scale + cumulative-tail block weights ----------------
__global__ void k_prep(const float* __restrict__ running_avg, const float* __restrict__ bw) {
    float one_minus = (float)(1.0 - 0.99);
    float ra = 0.99f * running_avg[0] + one_minus * (g_normsum / (float)BATCH);
    g_scale = sqrtf((float)DM) / ra;
    float tot = 0.f;
    for (int j = NB - 1; j >= 0; j--) { tot += bw[j]; g_cw[j] = tot / (float)NB; }
}

// ---------------- main fused kernel ----------------
struct SmemMain {
    float As[BK][BM + 4];       // x tile, [k][row]
    float Bs[BK][BN + 4];       // W_enc / W_dec tile, [k][col]
    float actsS[BN][BM + 4];    // acts tile, [feature][row]
    float sbenc[BN];
    float swdn[BN];
    float scwf[BN];
    int   segs[BN];
    int   runs[BN + 1];
    int   nrun;
};

__global__ __launch_bounds__(256) void k_main(
    const float* __restrict__ x, const float* __restrict__ W_enc,
    const float* __restrict__ b_enc, const float* __restrict__ W_dec,
    const int* __restrict__ seg)
{
    extern __shared__ char smraw[];
    SmemMain& sm = *reinterpret_cast<SmemMain*>(smraw);
    const int tid = threadIdx.x;
    const int tx = tid & 15, ty = tid >> 4;
    const int f0 = blockIdx.x * BN;
    const int b0 = blockIdx.y * BM;
    const float scale = g_scale;

    if (tid < BN) {
        int f = f0 + tid;
        int s = seg[f];
        sm.segs[tid]  = s;
        sm.sbenc[tid] = b_enc[f];
        sm.swdn[tid]  = g_wdn[f];
        sm.scwf[tid]  = g_cw[s];
    }
    __syncthreads();
    if (tid == 0) {  // seg-run detection (seg is monotone; usually 1 run/tile)
        int n = 0; sm.runs[0] = 0;
        for (int k = 1; k < BN; k++)
            if (sm.segs[k] != sm.segs[k - 1]) sm.runs[++n] = k;
        sm.runs[n + 1] = BN; sm.nrun = n + 1;
    }

    // ---- GEMM1: raw = x_tile @ W_enc_tile, K = 256 ----
    float acc[8][8];
#pragma unroll
    for (int i = 0; i < 8; i++)
#pragma unroll
        for (int j = 0; j < 8; j++) acc[i][j] = 0.f;

    for (int k0 = 0; k0 < DM; k0 += BK) {
#pragma unroll
        for (int i = 0; i < 8; i++) {
            int idx = i * 256 + tid;
            int row = idx >> 4, kk = idx & 15;
            sm.As[kk][row] = x[(size_t)(b0 + row) * DM + k0 + kk];
        }
#pragma unroll
        for (int i = 0; i < 8; i++) {
            int idx = i * 256 + tid;
            int kk = idx >> 7, col = idx & 127;
            sm.Bs[kk][col] = W_enc[(size_t)(k0 + kk) * NF + f0 + col];
        }
        __syncthreads();
#pragma unroll
        for (int k = 0; k < BK; k++) {
            float4 a0 = *(const float4*)&sm.As[k][ty * 8];
            float4 a1 = *(const float4*)&sm.As[k][ty * 8 + 4];
            float4 bb0 = *(const float4*)&sm.Bs[k][tx * 8];
            float4 bb1 = *(const float4*)&sm.Bs[k][tx * 8 + 4];
            float a[8] = {a0.x, a0.y, a0.z, a0.w, a1.x, a1.y, a1.z, a1.w};
            float b[8] = {bb0.x, bb0.y, bb0.z, bb0.w, bb1.x, bb1.y, bb1.z, bb1.w};
#pragma unroll
            for (int i = 0; i < 8; i++)
#pragma unroll
                for (int j = 0; j < 8; j++) acc[i][j] = fmaf(a[i], b[j], acc[i][j]);
        }
        __syncthreads();
    }

    // ---- epilogue: relu + L1/L0 scalar terms, stash acts to smem ----
    float l1p = 0.f; int l0p = 0;
#pragma unroll
    for (int j = 0; j < 8; j++) {
        int col = tx * 8 + j;
        float be = sm.sbenc[col], wn = sm.swdn[col], cw = sm.scwf[col];
#pragma unroll
        for (int i = 0; i < 8; i++) {
            float act = fmaf(scale, acc[i][j], be);
            act = fmaxf(act, 0.f);
            if (act > 0.f) {
                l0p++;
                // log(a*wn + 0.1) - log(0.1) == log1p(10*a*wn)
                l1p += cw * __logf(fmaf(10.f * wn, act, 1.f));
            }
            sm.actsS[col][ty * 8 + i] = act;
        }
    }
#pragma unroll
    for (int o = 16; o > 0; o >>= 1) {
        l1p += __shfl_down_sync(0xffffffffu, l1p, o);
        l0p += __shfl_down_sync(0xffffffffu, l0p, o);
    }
    if ((tid & 31) == 0) {
        atomicAdd(&g_l1, (double)l1p);
        atomicAdd(&g_l0, (unsigned long long)l0p);
    }
    __syncthreads();

    // ---- GEMM2 per seg-run: acts @ W_dec -> atomic accumulate into block ----
    const int nrun = sm.nrun;
    for (int r = 0; r < nrun; r++) {
        const int ka = sm.runs[r], kb = sm.runs[r + 1];
        const int blk = sm.segs[ka];
        float* dstbase = g_blockacc + ((size_t)blk * BATCH + b0) * DM;
        for (int dh = 0; dh < 2; dh++) {
            float c[8][8];
#pragma unroll
            for (int i = 0; i < 8; i++)
#pragma unroll
                for (int j = 0; j < 8; j++) c[i][j] = 0.f;

            for (int k0 = ka & ~(BK - 1); k0 < kb; k0 += BK) {
#pragma unroll
                for (int i = 0; i < 8; i++) {
                    int idx = i * 256 + tid;
                    int kk = idx >> 7, col = idx & 127;
                    sm.Bs[kk][col] = W_dec[(size_t)(f0 + k0 + kk) * DM + dh * 128 + col];
                }
                __syncthreads();
#pragma unroll
                for (int k = 0; k < BK; k++) {
                    int kk = k0 + k;
                    if (kk >= ka && kk < kb) {  // uniform predicate (run bounds are CTA-uniform)
                        float4 a0 = *(const float4*)&sm.actsS[kk][ty * 8];
                        float4 a1 = *(const float4*)&sm.actsS[kk][ty * 8 + 4];
                        float4 bb0 = *(const float4*)&sm.Bs[k][tx * 8];
                        float4 bb1 = *(const float4*)&sm.Bs[k][tx * 8 + 4];
                        float a[8] = {a0.x, a0.y, a0.z, a0.w, a1.x, a1.y, a1.z, a1.w};
                        float b[8] = {bb0.x, bb0.y, bb0.z, bb0.w, bb1.x, bb1.y, bb1.z, bb1.w};
#pragma unroll
                        for (int i = 0; i < 8; i++)
#pragma unroll
                            for (int j = 0; j < 8; j++) c[i][j] = fmaf(a[i], b[j], c[i][j]);
                    }
                }
                __syncthreads();
            }
#pragma unroll
            for (int i = 0; i < 8; i++) {
                float* dst = dstbase + (size_t)(ty * 8 + i) * DM + dh * 128 + tx * 8;
#pragma unroll
                for (int j = 0; j < 8; j++) atomicAdd(&dst[j], c[i][j]);
            }
        }
    }
}

// ---------------- per-row cumulative-block MSE ----------------
__global__ void k_mse(const float* __restrict__ x, const float* __restrict__ b_dec,
                      const float* __restrict__ bw) {
    __shared__ float sbw[NB];
    __shared__ float red[8];
    int b = blockIdx.x, d = threadIdx.x;
    if (d < NB) sbw[d] = bw[d];
    __syncthreads();
    float xn = x[(size_t)b * DM + d] * g_scale;
    float cum = b_dec[d];
    float t = 0.f;
#pragma unroll
    for (int k = 0; k < NB; k++) {
        cum += g_blockacc[((size_t)k * BATCH + b) * DM + d];
        float diff = cum - xn;
        t += sbw[k] * diff * diff;
    }
#pragma unroll
    for (int o = 16; o > 0; o >>= 1) t += __shfl_down_sync(0xffffffffu, t, o);
    if ((d & 31) == 0) red[d >> 5] = t;
    __syncthreads();
    if (d < 8) {
        t = red[d];
#pragma unroll
        for (int o = 4; o > 0; o >>= 1) t += __shfl_down_sync(0xffu, t, o);
        if (d == 0) atomicAdd(&g_mse, (double)t);
    }
}

// ---------------- combine ----------------
__global__ void k_final(const float* __restrict__ l1_scale, float* __restrict__ out) {
    double mse = g_mse / ((double)NB * (double)BATCH);
    double l1  = g_l1 / (double)BATCH;
    float avg_l0 = (float)((double)g_l0 / (double)BATCH);
    float reg = l1_scale[0] * (avg_l0 < 100.0f ? (1.0f - 3e-4f) : (1.0f + 3e-4f));
    out[0] = (float)(mse + (double)reg * (double)l1);
}

// ---------------- launch ----------------
extern "C" void kernel_launch(void* const* d_in, const int* in_sizes, int n_in,
                              void* d_out, int out_size) {
    const float* x     = (const float*)d_in[0];
    const float* W_enc = (const float*)d_in[1];
    const float* b_enc = (const float*)d_in[2];
    const float* W_dec = (const float*)d_in[3];
    const float* b_dec = (const float*)d_in[4];
    const float* bw    = (const float*)d_in[5];
    const float* ravg  = (const float*)d_in[6];
    const float* l1s   = (const float*)d_in[7];
    const int*   seg   = (const int*)d_in[8];
    float* out = (float*)d_out;

    cudaFuncSetAttribute(k_main, cudaFuncAttributeMaxDynamicSharedMemorySize,
                         (int)sizeof(SmemMain));

    k_zero<<<2048, 256>>>();
    k_xnorm<<<BATCH / 8, 256>>>(x);
    k_wdn<<<NF / 8, 256>>>(W_dec);
    k_prep<<<1, 1>>>(ravg, bw);
    dim3 grid(NF / BN, BATCH / BM);
    k_main<<<grid, 256, sizeof(SmemMain)>>>(x, W_enc, b_enc, W_dec, seg);
    k_mse<<<BATCH, 256>>>(x, b_dec, bw);
    k_final<<<1, 1>>>(l1s, out);
}